// round 5
// baseline (speedup 1.0000x reference)
#include <cuda_runtime.h>

#define BSZ 4
#define D 16
#define MDIM 32
#define LTOT 81

#define ADD4(a, v) do { (a).x += (v).x; (a).y += (v).y; (a).z += (v).z; (a).w += (v).w; } while (0)

// Scratch: Q[b][p1][p2][jj][m] (jj = j3*3+j4), fp32. 1.18 MB -> L2 resident.
__device__ float g_Q[BSZ * D * D * 9 * MDIM];
__device__ float g_H[BSZ * LTOT];

// ---------------------------------------------------------------------------
// Pass 1: block (b,p1,p2) streams arr[b,p1,p2,:,:,:] (32 KB) with float4.
// thread = (m4: 8, p4: 16, p3h: 4); each thread loads 4 independent float4
// (p3 = p3h*4 + k) and accumulates into 3 p3-class accumulators.
// Two smem stages reduce p3h (4->1) then p4 -> j4 classes.
// Position weight: p contributes to class (p-1)%3 (if p>=1) and p%3 (if p<=14).
// ---------------------------------------------------------------------------
__global__ void __launch_bounds__(512, 3) pass1_kernel(const float4* __restrict__ arr) {
    __shared__ float4 S[4][3][16][8];   // [p3h][j3][p4][m4]  24 KB
    __shared__ float4 T[3][16][8];      // [j3][p4][m4]        6 KB

    const int b   = blockIdx.z;
    const int p1  = blockIdx.y;
    const int p2  = blockIdx.x;
    const int t   = threadIdx.x;
    const int m4  = t & 7;
    const int p4  = (t >> 3) & 15;
    const int p3h = t >> 7;              // 0..3

    const float4* __restrict__ src =
        arr + ((size_t)(((b * D + p1) * D + p2) * D + p3h * 4) * D + p4) * 8 + m4;

    // 4 independent loads first (MLP=4), then accumulate.
    float4 v0 = src[0 * D * 8];
    float4 v1 = src[1 * D * 8];
    float4 v2 = src[2 * D * 8];
    float4 v3 = src[3 * D * 8];

    float4 a0 = {0.f,0.f,0.f,0.f}, a1 = a0, a2 = a0;
#pragma unroll
    for (int k = 0; k < 4; ++k) {
        const float4 v = (k == 0) ? v0 : (k == 1) ? v1 : (k == 2) ? v2 : v3;
        const int p3 = p3h * 4 + k;
        if (p3 >= 1) {
            const int ja = (p3 - 1) % 3;
            if (ja == 0) ADD4(a0, v); else if (ja == 1) ADD4(a1, v); else ADD4(a2, v);
        }
        if (p3 <= 14) {
            const int jb = p3 % 3;
            if (jb == 0) ADD4(a0, v); else if (jb == 1) ADD4(a1, v); else ADD4(a2, v);
        }
    }
    S[p3h][0][p4][m4] = a0;
    S[p3h][1][p4][m4] = a1;
    S[p3h][2][p4][m4] = a2;
    __syncthreads();

    if (t < 384) {            // t = j3*128 + p4*8 + m4 : reduce p3h
        const int mm = t & 7;
        const int pp = (t >> 3) & 15;
        const int j3 = t >> 7;
        float4 s = S[0][j3][pp][mm];
        ADD4(s, S[1][j3][pp][mm]);
        ADD4(s, S[2][j3][pp][mm]);
        ADD4(s, S[3][j3][pp][mm]);
        T[j3][pp][mm] = s;
    }
    __syncthreads();

    if (t < 72) {             // t = jj*8 + m4 : reduce p4 -> j4 classes
        const int mm = t & 7;
        const int jj = t >> 3;       // j3*3 + j4
        const int j4 = jj % 3;
        const int j3 = jj / 3;
        float4 s = {0.f,0.f,0.f,0.f};
#pragma unroll
        for (int i = 0; i < 10; ++i) {
            const int p = 3 * (i >> 1) + j4 + (i & 1);
            ADD4(s, T[j3][p][mm]);
        }
        float4* __restrict__ qo = (float4*)g_Q;
        qo[(((((b * D + p1) * D + p2) * 9) + jj) * 8) + mm] = s;
    }
}

// ---------------------------------------------------------------------------
// Pass 2: block (c, b), 256 threads (8 warps).
//   E[c,m] = sum_n Bbasis[c,n] * M[n,m]
//   G[c,m] = sum over 100 (p1,p2) slices of Q (12-13 independent loads/warp)
//   H[b,c] = sum_m E[c,m]*G[c,m]
// ---------------------------------------------------------------------------
__global__ void __launch_bounds__(256) pass2_kernel(const float* __restrict__ Mmat,
                                                    const float* __restrict__ Bbasis) {
    __shared__ float E_s[32];
    __shared__ float part[8][32];

    const int c  = blockIdx.x;   // 0..80
    const int b  = blockIdx.y;   // 0..3
    const int t  = threadIdx.x;
    const int lane = t & 31;
    const int wp   = t >> 5;

    const int j4 = c % 3;
    const int j3 = (c / 3) % 3;
    const int j2 = (c / 9) % 3;
    const int j1 = c / 27;
    const int jj = j3 * 3 + j4;

    if (t < 32) {
        float e = 0.f;
#pragma unroll
        for (int n = 0; n < MDIM; ++n)
            e += Bbasis[c * MDIM + n] * Mmat[n * MDIM + t];
        E_s[t] = e;
    }

    float g = 0.f;
    for (int k = wp; k < 100; k += 8) {
        const int i1 = k / 10;
        const int i2 = k % 10;
        const int p1 = 3 * (i1 >> 1) + j1 + (i1 & 1);
        const int p2 = 3 * (i2 >> 1) + j2 + (i2 & 1);
        g += g_Q[((((b * D + p1) * D + p2) * 9) + jj) * MDIM + lane];
    }
    part[wp][lane] = g;
    __syncthreads();

    if (wp == 0) {
        float G = part[0][lane] + part[1][lane] + part[2][lane] + part[3][lane]
                + part[4][lane] + part[5][lane] + part[6][lane] + part[7][lane];
        float h = E_s[lane] * G;
#pragma unroll
        for (int o = 16; o; o >>= 1)
            h += __shfl_xor_sync(0xffffffffu, h, o);
        if (lane == 0) g_H[b * LTOT + c] = h;
    }
}

// ---------------------------------------------------------------------------
// Pass 3: out[b,n] = K * sum_c H[b,c] * Acoeff[n,c],  K = 1/(16 * 15^4)
// ---------------------------------------------------------------------------
__global__ void __launch_bounds__(128) pass3_kernel(const float* __restrict__ Acoeff,
                                                    float* __restrict__ out) {
    const int t = threadIdx.x;
    const int b = t >> 5;
    const int n = t & 31;
    const float K = 1.0f / (16.0f * 50625.0f);
    float s = 0.f;
#pragma unroll
    for (int c = 0; c < LTOT; ++c)
        s += g_H[b * LTOT + c] * Acoeff[n * LTOT + c];
    out[b * MDIM + n] = s * K;
}

extern "C" void kernel_launch(void* const* d_in, const int* in_sizes, int n_in,
                              void* d_out, int out_size) {
    const float4* arr   = (const float4*)d_in[0];  // [4,16,16,16,16,32]
    const float* Mmat   = (const float*)d_in[1];   // [32,32]
    const float* Acoeff = (const float*)d_in[2];   // [32,81]
    const float* Bbasis = (const float*)d_in[3];   // [81,32]
    float* out = (float*)d_out;                    // [4,32]

    dim3 g1(D, D, BSZ);                 // (p2, p1, b) = 1024 blocks
    pass1_kernel<<<g1, 512>>>(arr);

    dim3 g2(LTOT, BSZ);                 // (c, b) = 324 blocks
    pass2_kernel<<<g2, 256>>>(Mmat, Bbasis);

    pass3_kernel<<<1, 128>>>(Acoeff, out);
}

// round 6
// speedup vs baseline: 1.0017x; 1.0017x over previous
#include <cuda_runtime.h>

#define BSZ 4
#define D 16
#define MDIM 32
#define LTOT 81

#define ADD4(a, v) do { (a).x += (v).x; (a).y += (v).y; (a).z += (v).z; (a).w += (v).w; } while (0)

// Scratch: Q[slab][jj][m], slab=(b,p1,p2), jj=j3*3+j4. 1.18 MB -> L2 resident.
__device__ float g_Q[BSZ * D * D * 9 * MDIM];
__device__ float g_H[BSZ * LTOT];

// ---------------------------------------------------------------------------
// Pass 1: one WARP per slab (b,p1,p2). lane = (p4h:2, m4:3).
// Thread streams 64 float4: p3 = 0..15 (classes compile-time), p4 = p4h*4+p4l
// (4 owned values). Rotation trick keeps all accumulator indices compile-time:
//   accR[j3][r4] with j4 = (r4 + p4h) % 3, r4a = (p4l+2)%3, r4b = p4l%3.
// No shared memory, no __syncthreads. Butterfly shuffle over p4h, store.
// Position weight: p in class (p-1)%3 (if p>=1) and p%3 (if p<=14).
// ---------------------------------------------------------------------------
__global__ void __launch_bounds__(64) pass1_kernel(const float4* __restrict__ arr) {
    const int gtid = blockIdx.x * 64 + threadIdx.x;
    const int slab = gtid >> 5;           // 0..1023
    const int lane = gtid & 31;
    const int m4   = lane & 7;
    const int p4h  = lane >> 3;           // 0..3

    const float4* __restrict__ base = arr + (size_t)slab * 2048 + m4;

    float4 z = {0.f, 0.f, 0.f, 0.f};
    float4 accR[3][3] = {{z,z,z},{z,z,z},{z,z,z}};   // [j3][r4]

#pragma unroll
    for (int p4l = 0; p4l < 4; ++p4l) {
        const int p4 = p4h * 4 + p4l;
        float4 t0 = z, t1 = z, t2 = z;
#pragma unroll
        for (int p3 = 0; p3 < 16; ++p3) {
            float4 v = base[(p3 * 16 + p4) * 8];
            if (p3 >= 1) {
                const int ja = (p3 - 1) % 3;              // compile-time
                if (ja == 0) ADD4(t0, v); else if (ja == 1) ADD4(t1, v); else ADD4(t2, v);
            }
            if (p3 <= 14) {
                const int jb = p3 % 3;                    // compile-time
                if (jb == 0) ADD4(t0, v); else if (jb == 1) ADD4(t1, v); else ADD4(t2, v);
            }
        }
        const int ra = (p4l + 2) % 3;   // compile-time rotated class of (p4-1)%3
        const int rb = p4l % 3;         // compile-time rotated class of  p4   %3
        if (p4 >= 1) {                  // runtime only when p4l==0
            ADD4(accR[0][ra], t0); ADD4(accR[1][ra], t1); ADD4(accR[2][ra], t2);
        }
        if (p4 <= 14) {                 // runtime only when p4l==3
            ADD4(accR[0][rb], t0); ADD4(accR[1][rb], t1); ADD4(accR[2][rb], t2);
        }
    }

    // Un-rotate: acc[j3][j4] = accR[j3][(j4 - p4h) mod 3]  (select over 3 cases)
    const int rot = p4h % 3;            // p4h in 0..3 -> rot in {0,1,2,0}
    float4 acc[3][3];
#pragma unroll
    for (int j3 = 0; j3 < 3; ++j3) {
#pragma unroll
        for (int j4 = 0; j4 < 3; ++j4) {
            float4 a0 = accR[j3][j4];            // rot == 0
            float4 a1 = accR[j3][(j4 + 2) % 3];  // rot == 1
            float4 a2 = accR[j3][(j4 + 1) % 3];  // rot == 2
            acc[j3][j4] = (rot == 0) ? a0 : (rot == 1) ? a1 : a2;
        }
    }

    // Butterfly reduce over p4h (lane bits 3,4)
#pragma unroll
    for (int off = 8; off <= 16; off <<= 1) {
#pragma unroll
        for (int j3 = 0; j3 < 3; ++j3)
#pragma unroll
            for (int j4 = 0; j4 < 3; ++j4) {
                float4& a = acc[j3][j4];
                a.x += __shfl_xor_sync(0xffffffffu, a.x, off);
                a.y += __shfl_xor_sync(0xffffffffu, a.y, off);
                a.z += __shfl_xor_sync(0xffffffffu, a.z, off);
                a.w += __shfl_xor_sync(0xffffffffu, a.w, off);
            }
    }

    if (p4h == 0) {
        float4* __restrict__ qo = (float4*)g_Q;
#pragma unroll
        for (int jj = 0; jj < 9; ++jj)
            qo[slab * 72 + jj * 8 + m4] = acc[jj / 3][jj % 3];
    }
}

// ---------------------------------------------------------------------------
// Pass 2: block (c, b), 256 threads (8 warps).
//   E[c,m] = sum_n Bbasis[c,n] * M[n,m]
//   G[c,m] = sum over 100 (p1,p2) slices of Q (12-13 independent loads/warp)
//   H[b,c] = sum_m E[c,m]*G[c,m]
// ---------------------------------------------------------------------------
__global__ void __launch_bounds__(256) pass2_kernel(const float* __restrict__ Mmat,
                                                    const float* __restrict__ Bbasis) {
    __shared__ float E_s[32];
    __shared__ float part[8][32];

    const int c  = blockIdx.x;   // 0..80
    const int b  = blockIdx.y;   // 0..3
    const int t  = threadIdx.x;
    const int lane = t & 31;
    const int wp   = t >> 5;

    const int j4 = c % 3;
    const int j3 = (c / 3) % 3;
    const int j2 = (c / 9) % 3;
    const int j1 = c / 27;
    const int jj = j3 * 3 + j4;

    if (t < 32) {
        float e = 0.f;
#pragma unroll
        for (int n = 0; n < MDIM; ++n)
            e += Bbasis[c * MDIM + n] * Mmat[n * MDIM + t];
        E_s[t] = e;
    }

    float g = 0.f;
    for (int k = wp; k < 100; k += 8) {
        const int i1 = k / 10;
        const int i2 = k % 10;
        const int p1 = 3 * (i1 >> 1) + j1 + (i1 & 1);
        const int p2 = 3 * (i2 >> 1) + j2 + (i2 & 1);
        g += g_Q[((((b * D + p1) * D + p2) * 9) + jj) * MDIM + lane];
    }
    part[wp][lane] = g;
    __syncthreads();

    if (wp == 0) {
        float G = part[0][lane] + part[1][lane] + part[2][lane] + part[3][lane]
                + part[4][lane] + part[5][lane] + part[6][lane] + part[7][lane];
        float h = E_s[lane] * G;
#pragma unroll
        for (int o = 16; o; o >>= 1)
            h += __shfl_xor_sync(0xffffffffu, h, o);
        if (lane == 0) g_H[b * LTOT + c] = h;
    }
}

// ---------------------------------------------------------------------------
// Pass 3: out[b,n] = K * sum_c H[b,c] * Acoeff[n,c],  K = 1/(16 * 15^4)
// ---------------------------------------------------------------------------
__global__ void __launch_bounds__(128) pass3_kernel(const float* __restrict__ Acoeff,
                                                    float* __restrict__ out) {
    const int t = threadIdx.x;
    const int b = t >> 5;
    const int n = t & 31;
    const float K = 1.0f / (16.0f * 50625.0f);
    float s = 0.f;
#pragma unroll
    for (int c = 0; c < LTOT; ++c)
        s += g_H[b * LTOT + c] * Acoeff[n * LTOT + c];
    out[b * MDIM + n] = s * K;
}

extern "C" void kernel_launch(void* const* d_in, const int* in_sizes, int n_in,
                              void* d_out, int out_size) {
    const float4* arr   = (const float4*)d_in[0];  // [4,16,16,16,16,32]
    const float* Mmat   = (const float*)d_in[1];   // [32,32]
    const float* Acoeff = (const float*)d_in[2];   // [32,81]
    const float* Bbasis = (const float*)d_in[3];   // [81,32]
    float* out = (float*)d_out;                    // [4,32]

    pass1_kernel<<<512, 64>>>(arr);                // 1024 warps, 1 slab each

    dim3 g2(LTOT, BSZ);                            // (c, b) = 324 blocks
    pass2_kernel<<<g2, 256>>>(Mmat, Bbasis);

    pass3_kernel<<<1, 128>>>(Acoeff, out);
}

// round 7
// speedup vs baseline: 1.0496x; 1.0479x over previous
#include <cuda_runtime.h>

#define BSZ 4
#define D 16
#define MDIM 32
#define LTOT 81
#define NBLK 512
#define NPASS2 (LTOT * BSZ)   // 324

#define ADD4(a, v) do { (a).x += (v).x; (a).y += (v).y; (a).z += (v).z; (a).w += (v).w; } while (0)

// Scratch. Q[slab][jj][m], slab=(b,p1,p2) 0..1023, jj=j3*3+j4. 1.18 MB.
__device__ float g_Q[BSZ * D * D * 9 * MDIM];
__device__ float g_H[BSZ * LTOT];
__device__ unsigned int g_c1 = 0;
__device__ unsigned int g_c2 = 0;

// ---------------------------------------------------------------------------
// Single persistent kernel: 512 blocks x 128 threads, all co-resident.
// Phase A: block k reduces slabs 2k, 2k+1  (arr -> Q)
// barrier1 (atomic counter + fence)
// Phase B: blocks 0..323: (c,b) cleanup     (Q -> H)
// barrier2
// Phase C: block 0: out[b,n] = K * sum_c H[b,c]*Acoeff[n,c]; reset counters.
// ---------------------------------------------------------------------------
__global__ void __launch_bounds__(128, 4)
fused_kernel(const float4* __restrict__ arr,
             const float* __restrict__ Mmat,
             const float* __restrict__ Acoeff,
             const float* __restrict__ Bbasis,
             float* __restrict__ out) {
    __shared__ float4 S[16][3][8];    // [p4][j3][m4]  6 KB
    __shared__ float  E_s[32];
    __shared__ float  part[4][32];

    const int t    = threadIdx.x;
    const int m4   = t & 7;
    const int p4   = t >> 3;          // 0..15
    const int lane = t & 31;
    const int wp   = t >> 5;

    // ---------------- Phase A: two slabs per block ----------------
#pragma unroll
    for (int s = 0; s < 2; ++s) {
        const int slab = blockIdx.x * 2 + s;
        const float4* __restrict__ base = arr + (size_t)slab * 2048 + p4 * 8 + m4;

        float4 t0 = {0.f,0.f,0.f,0.f}, t1 = t0, t2 = t0;
#pragma unroll
        for (int p3 = 0; p3 < 16; ++p3) {
            float4 v = base[p3 * 128];
            if (p3 >= 1) {
                const int ja = (p3 - 1) % 3;   // compile-time
                if (ja == 0) ADD4(t0, v); else if (ja == 1) ADD4(t1, v); else ADD4(t2, v);
            }
            if (p3 <= 14) {
                const int jb = p3 % 3;         // compile-time
                if (jb == 0) ADD4(t0, v); else if (jb == 1) ADD4(t1, v); else ADD4(t2, v);
            }
        }
        S[p4][0][m4] = t0;
        S[p4][1][m4] = t1;
        S[p4][2][m4] = t2;
        __syncthreads();

        if (t < 72) {                 // t = jj*8 + mm : reduce p4 -> j4 classes
            const int mm = t & 7;
            const int jj = t >> 3;    // j3*3 + j4
            const int j4 = jj % 3;
            const int j3 = jj / 3;
            float4 q = {0.f,0.f,0.f,0.f};
#pragma unroll
            for (int i = 0; i < 10; ++i) {
                const int p = 3 * (i >> 1) + j4 + (i & 1);
                ADD4(q, S[p][j3][mm]);
            }
            ((float4*)g_Q)[slab * 72 + jj * 8 + mm] = q;
        }
        __syncthreads();
    }

    // ---------------- barrier 1 ----------------
    if (t == 0) {
        __threadfence();
        atomicAdd(&g_c1, 1u);
    }
    if (blockIdx.x >= NPASS2) return;          // arrived; no more work

    if (t == 0) {
        while (atomicAdd(&g_c1, 0u) < (unsigned)NBLK) __nanosleep(64);
    }
    __syncthreads();
    __threadfence();

    // ---------------- Phase B: one (c,b) per block ----------------
    const int c = blockIdx.x % LTOT;
    const int b = blockIdx.x / LTOT;

    const int j4 = c % 3;
    const int j3 = (c / 3) % 3;
    const int j2 = (c / 9) % 3;
    const int j1 = c / 27;
    const int jj = j3 * 3 + j4;

    if (t < 32) {
        float e = 0.f;
#pragma unroll
        for (int n = 0; n < MDIM; ++n)
            e += Bbasis[c * MDIM + n] * Mmat[n * MDIM + t];
        E_s[t] = e;
    }

    float g = 0.f;
    for (int k = wp; k < 100; k += 4) {        // 25 loads per warp, independent
        const int i1 = k / 10;
        const int i2 = k % 10;
        const int p1 = 3 * (i1 >> 1) + j1 + (i1 & 1);
        const int p2 = 3 * (i2 >> 1) + j2 + (i2 & 1);
        g += g_Q[(((b * D + p1) * D + p2) * 9 + jj) * MDIM + lane];
    }
    part[wp][lane] = g;
    __syncthreads();

    if (wp == 0) {
        float G = part[0][lane] + part[1][lane] + part[2][lane] + part[3][lane];
        float h = E_s[lane] * G;
#pragma unroll
        for (int o = 16; o; o >>= 1)
            h += __shfl_xor_sync(0xffffffffu, h, o);
        if (lane == 0) g_H[b * LTOT + c] = h;
    }

    // ---------------- barrier 2 ----------------
    if (t == 0) {
        __threadfence();
        atomicAdd(&g_c2, 1u);
    }
    if (blockIdx.x != 0) return;

    if (t == 0) {
        while (atomicAdd(&g_c2, 0u) < (unsigned)NPASS2) __nanosleep(64);
    }
    __syncthreads();
    __threadfence();

    // ---------------- Phase C: block 0 finishes ----------------
    {
        const int bb = t >> 5;
        const int n  = t & 31;
        const float K = 1.0f / (16.0f * 50625.0f);
        float sum = 0.f;
#pragma unroll
        for (int cc = 0; cc < LTOT; ++cc)
            sum += g_H[bb * LTOT + cc] * Acoeff[n * LTOT + cc];
        out[bb * MDIM + n] = sum * K;
    }
    __syncthreads();
    if (t == 0) {                    // reset for next graph replay
        g_c1 = 0;
        g_c2 = 0;
        __threadfence();
    }
}

extern "C" void kernel_launch(void* const* d_in, const int* in_sizes, int n_in,
                              void* d_out, int out_size) {
    const float4* arr   = (const float4*)d_in[0];  // [4,16,16,16,16,32]
    const float* Mmat   = (const float*)d_in[1];   // [32,32]
    const float* Acoeff = (const float*)d_in[2];   // [32,81]
    const float* Bbasis = (const float*)d_in[3];   // [81,32]
    float* out = (float*)d_out;                    // [4,32]

    fused_kernel<<<NBLK, 128>>>(arr, Mmat, Acoeff, Bbasis, out);
}

// round 8
// speedup vs baseline: 1.1149x; 1.0621x over previous
#include <cuda_runtime.h>
#include <cstdint>

#define BSZ 4
#define D 16
#define MDIM 32
#define LTOT 81

#define ADD4(a, v) do { (a).x += (v).x; (a).y += (v).y; (a).z += (v).z; (a).w += (v).w; } while (0)

// Q[slab][jj][m], slab=(b,p1,p2) 0..1023, jj=j3*3+j4. 1.18 MB.
__device__ float g_Q[BSZ * D * D * 9 * MDIM];
__device__ float g_H[BSZ * LTOT];

__device__ __forceinline__ uint32_t smem_u32(const void* p) {
    uint32_t a;
    asm("{ .reg .u64 t; cvta.to.shared.u64 t, %1; cvt.u32.u64 %0, t; }" : "=r"(a) : "l"(p));
    return a;
}
__device__ __forceinline__ void mbar_init(uint32_t mbar, uint32_t cnt) {
    asm volatile("mbarrier.init.shared.b64 [%0], %1;" :: "r"(mbar), "r"(cnt) : "memory");
}
__device__ __forceinline__ void mbar_expect_tx(uint32_t mbar, uint32_t bytes) {
    asm volatile("mbarrier.arrive.expect_tx.shared.b64 _, [%0], %1;" :: "r"(mbar), "r"(bytes) : "memory");
}
__device__ __forceinline__ void mbar_wait(uint32_t mbar, uint32_t parity) {
    asm volatile(
        "{\n\t.reg .pred P;\n\t"
        "WAIT_%=:\n\t"
        "mbarrier.try_wait.parity.acquire.cta.shared::cta.b64 P, [%0], %1, 0x989680;\n\t"
        "@!P bra WAIT_%=;\n\t}"
        :: "r"(mbar), "r"(parity) : "memory");
}
__device__ __forceinline__ void bulk_g2s(uint32_t dst, const void* src, uint32_t bytes, uint32_t mbar) {
    asm volatile(
        "cp.async.bulk.shared::cta.global.mbarrier::complete_tx::bytes [%0], [%1], %2, [%3];"
        :: "r"(dst), "l"(src), "r"(bytes), "r"(mbar) : "memory");
}
__device__ __forceinline__ void fence_proxy_async_cta() {
    asm volatile("fence.proxy.async.shared::cta;" ::: "memory");
}

// ---------------------------------------------------------------------------
// Pass 1 (TMA-pipelined): CTA k owns slabs 2k, 2k+1. 4-stage 8KB smem ring.
// Chunk q of slab = p3 in [4q, 4q+4) x [p4 16][m 32] floats, contiguous 8KB.
// 128 consumers: thread (m4, p4) accumulates p3-classes in registers,
// then 2-stage smem reduce -> g_Q[slab][jj][m].
// Position weight: p in class (p-1)%3 (if p>=1) and p%3 (if p<=14).
// ---------------------------------------------------------------------------
#define CHUNK_BYTES 8192
__global__ void __launch_bounds__(128) pass1_kernel(const char* __restrict__ arr) {
    __shared__ __align__(16) float buf[4][4 * 16 * 32];     // 4 x 8KB ring
    __shared__ float4 S[16][3][8];                           // [p4][j3][m4] 6KB
    __shared__ __align__(8) unsigned long long mbar[4];

    const int t  = threadIdx.x;
    const int m4 = t & 7;
    const int p4 = t >> 3;          // 0..15

    uint32_t mb[4];
#pragma unroll
    for (int q = 0; q < 4; ++q) mb[q] = smem_u32(&mbar[q]);

    if (t == 0) {
#pragma unroll
        for (int q = 0; q < 4; ++q) mbar_init(mb[q], 1);
    }
    __syncthreads();

    const int slab0 = blockIdx.x * 2;
    const char* __restrict__ src0 = arr + (size_t)slab0 * 32768;

    // Prologue: issue all 4 chunks of slab 0.
    if (t == 0) {
#pragma unroll
        for (int q = 0; q < 4; ++q) {
            mbar_expect_tx(mb[q], CHUNK_BYTES);
            bulk_g2s(smem_u32(&buf[q][0]), src0 + q * CHUNK_BYTES, CHUNK_BYTES, mb[q]);
        }
    }

#pragma unroll
    for (int s = 0; s < 2; ++s) {
        const int slab = slab0 + s;
        float4 t0 = {0.f,0.f,0.f,0.f}, t1 = t0, t2 = t0;

#pragma unroll
        for (int q = 0; q < 4; ++q) {
            mbar_wait(mb[q], (uint32_t)s);

            const float4* __restrict__ bp =
                (const float4*)(&buf[q][0]) + p4 * 8 + m4;
#pragma unroll
            for (int k = 0; k < 4; ++k) {
                const int p3 = q * 4 + k;           // compile-time
                float4 v = bp[k * 128];
                if (p3 >= 1) {
                    const int ja = (p3 - 1) % 3;
                    if (ja == 0) ADD4(t0, v); else if (ja == 1) ADD4(t1, v); else ADD4(t2, v);
                }
                if (p3 <= 14) {
                    const int jb = p3 % 3;
                    if (jb == 0) ADD4(t0, v); else if (jb == 1) ADD4(t1, v); else ADD4(t2, v);
                }
            }
            __syncthreads();                        // all reads of buf[q] done
            if (s == 0 && t == 0) {                 // refill with slab1 chunk q
                fence_proxy_async_cta();
                mbar_expect_tx(mb[q], CHUNK_BYTES);
                bulk_g2s(smem_u32(&buf[q][0]),
                         src0 + 32768 + q * CHUNK_BYTES, CHUNK_BYTES, mb[q]);
            }
        }

        S[p4][0][m4] = t0;
        S[p4][1][m4] = t1;
        S[p4][2][m4] = t2;
        __syncthreads();

        if (t < 72) {               // t = jj*8 + mm : reduce p4 -> j4 classes
            const int mm = t & 7;
            const int jj = t >> 3;  // j3*3 + j4
            const int j4 = jj % 3;
            const int j3 = jj / 3;
            float4 qv = {0.f,0.f,0.f,0.f};
#pragma unroll
            for (int i = 0; i < 10; ++i) {
                const int p = 3 * (i >> 1) + j4 + (i & 1);
                ADD4(qv, S[p][j3][mm]);
            }
            ((float4*)g_Q)[slab * 72 + jj * 8 + mm] = qv;
        }
        __syncthreads();            // S reused next slab
    }
}

// ---------------------------------------------------------------------------
// Pass 2: block (c, b), 256 threads (8 warps).
// ---------------------------------------------------------------------------
__global__ void __launch_bounds__(256) pass2_kernel(const float* __restrict__ Mmat,
                                                    const float* __restrict__ Bbasis) {
    __shared__ float E_s[32];
    __shared__ float part[8][32];

    const int c  = blockIdx.x;
    const int b  = blockIdx.y;
    const int t  = threadIdx.x;
    const int lane = t & 31;
    const int wp   = t >> 5;

    const int j4 = c % 3;
    const int j3 = (c / 3) % 3;
    const int j2 = (c / 9) % 3;
    const int j1 = c / 27;
    const int jj = j3 * 3 + j4;

    if (t < 32) {
        float e = 0.f;
#pragma unroll
        for (int n = 0; n < MDIM; ++n)
            e += Bbasis[c * MDIM + n] * Mmat[n * MDIM + t];
        E_s[t] = e;
    }

    float g = 0.f;
    for (int k = wp; k < 100; k += 8) {
        const int i1 = k / 10;
        const int i2 = k % 10;
        const int p1 = 3 * (i1 >> 1) + j1 + (i1 & 1);
        const int p2 = 3 * (i2 >> 1) + j2 + (i2 & 1);
        g += g_Q[((((b * D + p1) * D + p2) * 9) + jj) * MDIM + lane];
    }
    part[wp][lane] = g;
    __syncthreads();

    if (wp == 0) {
        float G = part[0][lane] + part[1][lane] + part[2][lane] + part[3][lane]
                + part[4][lane] + part[5][lane] + part[6][lane] + part[7][lane];
        float h = E_s[lane] * G;
#pragma unroll
        for (int o = 16; o; o >>= 1)
            h += __shfl_xor_sync(0xffffffffu, h, o);
        if (lane == 0) g_H[b * LTOT + c] = h;
    }
}

// ---------------------------------------------------------------------------
// Pass 3: out[b,n] = K * sum_c H[b,c] * Acoeff[n,c],  K = 1/(16 * 15^4)
// ---------------------------------------------------------------------------
__global__ void __launch_bounds__(128) pass3_kernel(const float* __restrict__ Acoeff,
                                                    float* __restrict__ out) {
    const int t = threadIdx.x;
    const int b = t >> 5;
    const int n = t & 31;
    const float K = 1.0f / (16.0f * 50625.0f);
    float s = 0.f;
#pragma unroll
    for (int c = 0; c < LTOT; ++c)
        s += g_H[b * LTOT + c] * Acoeff[n * LTOT + c];
    out[b * MDIM + n] = s * K;
}

extern "C" void kernel_launch(void* const* d_in, const int* in_sizes, int n_in,
                              void* d_out, int out_size) {
    const char* arr     = (const char*)d_in[0];    // [4,16,16,16,16,32] f32
    const float* Mmat   = (const float*)d_in[1];   // [32,32]
    const float* Acoeff = (const float*)d_in[2];   // [32,81]
    const float* Bbasis = (const float*)d_in[3];   // [81,32]
    float* out = (float*)d_out;                    // [4,32]

    pass1_kernel<<<512, 128>>>(arr);               // 2 slabs per CTA

    dim3 g2(LTOT, BSZ);                            // (c, b) = 324 blocks
    pass2_kernel<<<g2, 256>>>(Mmat, Bbasis);

    pass3_kernel<<<1, 128>>>(Acoeff, out);
}